// round 15
// baseline (speedup 1.0000x reference)
#include <cuda_runtime.h>
#include <cuda_fp16.h>
#include <math.h>

#define V    262144         // 64^3
#define PD   66             // padded dim
#define PS   (PD*PD)        // 4356
#define PV   (PD*PD*PD)     // 287496
#define PBASE (PS + PD + 1) // offset of voxel (0,0,0) in padded volume
#define EPSV 1e-5f

typedef unsigned long long u64;

__device__ __forceinline__ u64 ffma2(u64 a, u64 b, u64 c) {
    u64 d;
    asm("fma.rn.f32x2 %0, %1, %2, %3;" : "=l"(d) : "l"(a), "l"(b), "l"(c));
    return d;
}
__device__ __forceinline__ u64 pack2(float lo, float hi) {
    u64 r;
    asm("mov.b64 %0, {%1, %2};" : "=l"(r) : "f"(lo), "f"(hi));
    return r;
}
__device__ __forceinline__ float2 unpack2(u64 v) {
    float2 r;
    asm("mov.b64 {%0, %1}, %2;" : "=f"(r.x), "=f"(r.y) : "l"(v));
    return r;
}

// ---------------- scratch (__device__ globals; no allocation) ----------------
__device__ float  g_ft[PV * 8];      // zero-padded fp32 feat [z][y][x][8] (conv_off)
__device__ float4 g_fth[PV];         // zero-padded fp16 feat [y][x][z][8 halves] (gather; z fastest)
__device__ float g_off[18 * V];
__device__ float g_conv[16 * V];
__device__ float g_bnsum[18];
__device__ float g_bnsq[18];
__device__ float g_gsum[4];
__device__ float g_gsq[4];

// ---------------- kernel 1: pad+transpose f -> fp32 [z][y][x] & fp16 [y][x][z] ----------------
__global__ void k_transpose(const float* __restrict__ f) {
    int tid = threadIdx.x;
    if (blockIdx.x == 0 && tid < 22) {
        if (tid < 18) { g_bnsum[tid] = 0.f; g_bnsq[tid] = 0.f; }
        else          { g_gsum[tid - 18] = 0.f; g_gsq[tid - 18] = 0.f; }
    }
    int pv = blockIdx.x * blockDim.x + tid;
    if (pv >= PV) return;
    int z = pv / PS, r = pv % PS, y = r / PD, x = r % PD;
    float4 a = make_float4(0.f, 0.f, 0.f, 0.f), b = a;
    if (z >= 1 && z <= 64 && y >= 1 && y <= 64 && x >= 1 && x <= 64) {
        int v = (((z - 1) << 6) + (y - 1) << 6) + (x - 1);
        a.x = f[0 * V + v]; a.y = f[1 * V + v]; a.z = f[2 * V + v]; a.w = f[3 * V + v];
        b.x = f[4 * V + v]; b.y = f[5 * V + v]; b.z = f[6 * V + v]; b.w = f[7 * V + v];
    }
    float4* dst = reinterpret_cast<float4*>(g_ft);
    dst[pv * 2 + 0] = a;
    dst[pv * 2 + 1] = b;

    float4 hp;
    __half2* hh = reinterpret_cast<__half2*>(&hp);
    hh[0] = __floats2half2_rn(a.x, a.y);
    hh[1] = __floats2half2_rn(a.z, a.w);
    hh[2] = __floats2half2_rn(b.x, b.y);
    hh[3] = __floats2half2_rn(b.z, b.w);
    g_fth[y * PS + x * PD + z] = hp;    // z-fastest layout (scattered store)
}

// ---------------- kernel 2: offset conv3d, lane-pair channel split (R10/R14 version) ----------------
__global__ void __launch_bounds__(256, 2)
k_conv_off(const float* __restrict__ offw, const float* __restrict__ offb) {
    __shared__ u64  sw2[27 * 8 * 9];   // [tap][ci][pair p] = (w[p], w[p+9])
    __shared__ int  srow[9];
    __shared__ u64  sbias2[9];
    int tid = threadIdx.x;
    for (int i = tid; i < 1944; i += 256) {
        int p = i % 9, tc = i / 9, ci = tc % 8, tap = tc / 8;
        sw2[i] = pack2(offw[(p * 8 + ci) * 27 + tap],
                       offw[((p + 9) * 8 + ci) * 27 + tap]);
    }
    if (tid < 9) {
        int dz = tid / 3 - 1, dy = tid % 3 - 1;
        srow[tid] = (dz * PS + dy * PD - 1) * 2;
        sbias2[tid] = pack2(offb[tid], offb[tid + 9]);
    }
    __syncthreads();

    int t    = blockIdx.x * 256 + tid;   // 131072 threads
    int pi   = t >> 1;                   // 65536 voxel-groups of 4
    int half = t & 1;                    // 0: ci 0-3, 1: ci 4-7
    int h4 = (pi & 15) << 2;
    int w  = (pi >> 4) & 63;
    int d  = pi >> 10;
    int pc = (d * PS + w * PD + h4 + PBASE) * 2 + half;
    int v0 = pi << 2;
    int lane = tid & 31;

    const float4* base = reinterpret_cast<const float4*>(g_ft);

    u64 acc2[9][4];
#pragma unroll
    for (int p = 0; p < 9; p++) {
        u64 b = half ? pack2(0.f, 0.f) : sbias2[p];
        acc2[p][0] = b; acc2[p][1] = b; acc2[p][2] = b; acc2[p][3] = b;
    }

#pragma unroll 1
    for (int t9 = 0; t9 < 9; t9++) {
        int rb = pc + srow[t9];
        float4 in4[6];                     // 6 x-positions, this thread's ci-half
#pragma unroll
        for (int j = 0; j < 6; j++) in4[j] = base[rb + 2 * j];
        const float* vals = reinterpret_cast<const float*>(in4);  // vals[pos*4 + c]

#pragma unroll
        for (int dx = 0; dx < 3; dx++) {
#pragma unroll
            for (int c = 0; c < 4; c++) {
                u64 a0 = pack2(vals[(dx + 0) * 4 + c], vals[(dx + 0) * 4 + c]);
                u64 a1 = pack2(vals[(dx + 1) * 4 + c], vals[(dx + 1) * 4 + c]);
                u64 a2 = pack2(vals[(dx + 2) * 4 + c], vals[(dx + 2) * 4 + c]);
                u64 a3 = pack2(vals[(dx + 3) * 4 + c], vals[(dx + 3) * 4 + c]);
                const u64* wp = &sw2[((t9 * 3 + dx) * 8 + half * 4 + c) * 9];
#pragma unroll
                for (int p = 0; p < 9; p++) {
                    u64 wv = wp[p];
                    acc2[p][0] = ffma2(a0, wv, acc2[p][0]);
                    acc2[p][1] = ffma2(a1, wv, acc2[p][1]);
                    acc2[p][2] = ffma2(a2, wv, acc2[p][2]);
                    acc2[p][3] = ffma2(a3, wv, acc2[p][3]);
                }
            }
        }
    }

    // pair combine (float-wise), split store, parity-preserving stats
#pragma unroll
    for (int p = 0; p < 9; p++) {
        float2 q0 = unpack2(acc2[p][0]);
        float2 q1 = unpack2(acc2[p][1]);
        float2 q2 = unpack2(acc2[p][2]);
        float2 q3 = unpack2(acc2[p][3]);
        float f0 = q0.x + __shfl_xor_sync(0xFFFFFFFFu, q0.x, 1);
        float g0 = q0.y + __shfl_xor_sync(0xFFFFFFFFu, q0.y, 1);
        float f1 = q1.x + __shfl_xor_sync(0xFFFFFFFFu, q1.x, 1);
        float g1 = q1.y + __shfl_xor_sync(0xFFFFFFFFu, q1.y, 1);
        float f2 = q2.x + __shfl_xor_sync(0xFFFFFFFFu, q2.x, 1);
        float g2 = q2.y + __shfl_xor_sync(0xFFFFFFFFu, q2.y, 1);
        float f3 = q3.x + __shfl_xor_sync(0xFFFFFFFFu, q3.x, 1);
        float g3 = q3.y + __shfl_xor_sync(0xFFFFFFFFu, q3.y, 1);
        float4 st = half ? make_float4(g0, g1, g2, g3)
                         : make_float4(f0, f1, f2, f3);
        int oc = half ? (p + 9) : p;
        *reinterpret_cast<float4*>(&g_off[oc * V + v0]) = st;

        float s = st.x + st.y + st.z + st.w;
        float q = st.x * st.x + st.y * st.y + st.z * st.z + st.w * st.w;
#pragma unroll
        for (int off = 16; off >= 2; off >>= 1) {
            s += __shfl_xor_sync(0xFFFFFFFFu, s, off);
            q += __shfl_xor_sync(0xFFFFFFFFu, q, off);
        }
        if (lane < 2) {
            atomicAdd(&g_bnsum[oc], s);
            atomicAdd(&g_bnsq[oc], q);
        }
    }
}

// ---------------- kernel 3: BN-finalize prologue + BN+tanh, cumsum,
//                  z-fastest fp16 gather, FFMA2 dcn conv, GN stats ----------------
__global__ void __launch_bounds__(256, 2)
k_main(const float* __restrict__ dcnw, const float* __restrict__ dcnb,
       const float* __restrict__ bng, const float* __restrict__ bnb) {
    __shared__ u64 sw2[9 * 8 * 8];     // [k][ci][pair p] = (w[p], w[p+8])
    __shared__ u64 sb2[8];
    __shared__ float sbns[18], sbnt[18];
    int tid = threadIdx.x;
    for (int i = tid; i < 576; i += 256) {
        int p = i & 7, kc = i >> 3, ci = kc % 8, k = kc / 8;
        sw2[i] = pack2(dcnw[p * 72 + ci * 9 + k], dcnw[(p + 8) * 72 + ci * 9 + k]);
    }
    if (tid < 8) sb2[tid] = pack2(dcnb[tid], dcnb[tid + 8]);
    if (tid >= 32 && tid < 50) {            // BN finalize on a separate warp
        int j = tid - 32;
        float mean = g_bnsum[j] * (1.0f / V);
        float var  = g_bnsq[j] * (1.0f / V) - mean * mean;
        float s = bng[j] * rsqrtf(var + EPSV);
        sbns[j] = s;
        sbnt[j] = bnb[j] - mean * s;
    }
    __syncthreads();

    int v = blockIdx.x * 256 + tid;
    int h = v & 63, w = (v >> 6) & 63, d = v >> 12;

    float zo[9], yo[9];
#pragma unroll
    for (int j = 0; j < 9; j++)
        zo[j] = tanhf(fmaf(g_off[j * V + v], sbns[j], sbnt[j]));
#pragma unroll
    for (int j = 0; j < 9; j++)
        yo[j] = tanhf(fmaf(g_off[(9 + j) * V + v], sbns[9 + j], sbnt[9 + j]));

#pragma unroll
    for (int k = 5; k < 9; k++) { zo[k] += zo[k - 1]; yo[k] += yo[k - 1]; }
#pragma unroll
    for (int k = 3; k >= 0; k--) { zo[k] += zo[k + 1]; yo[k] += yo[k + 1]; }

    u64 acc2[8];
#pragma unroll
    for (int p = 0; p < 8; p++) acc2[p] = sb2[p];

#pragma unroll
    for (int k = 0; k < 9; k++) {
        float zf = (float)d + zo[k];
        float yf = (float)w + yo[k];
        int   xi = h + k - 4;
        float valid = ((unsigned)xi < 63u) ? 1.f : 0.f;
        int   xc = min(max(xi, 0), 63);

        int zb = (int)floorf(zf);
        int yb = (int)floorf(yf);
        int z0 = min(max(zb, 0), 63),  z1 = min(max(zb + 1, 0), 63);
        int y0 = min(max(yb, 0), 63),  y1 = min(max(yb + 1, 0), 63);

        float wz0 = (float)z1 - zf, wz1 = zf - (float)z0;
        float wy0 = (float)y1 - yf, wy1 = yf - (float)y0;

        __half2 c00 = __float2half2_rn(wz0 * wy0 * valid);   // (z0, y0)
        __half2 c01 = __float2half2_rn(wz0 * wy1 * valid);   // (z0, y1)
        __half2 c10 = __float2half2_rn(wz1 * wy0 * valid);   // (z1, y0)
        __half2 c11 = __float2half2_rn(wz1 * wy1 * valid);   // (z1, y1)

        // z-fastest layout: index = y*PS + x*PD + z (+PBASE); z-pairs adjacent
        int b0 = y0 * PS + xc * PD + PBASE;
        int b1 = y1 * PS + xc * PD + PBASE;
        float4 A0 = g_fth[b0 + z0];     // (z0, y0)
        float4 A1 = g_fth[b0 + z1];     // (z1, y0)  -- adjacent 16B
        float4 B0 = g_fth[b1 + z0];     // (z0, y1)
        float4 B1 = g_fth[b1 + z1];     // (z1, y1)  -- adjacent 16B
        const __half2* A0h = reinterpret_cast<const __half2*>(&A0);
        const __half2* A1h = reinterpret_cast<const __half2*>(&A1);
        const __half2* B0h = reinterpret_cast<const __half2*>(&B0);
        const __half2* B1h = reinterpret_cast<const __half2*>(&B1);

        float dv[8];
#pragma unroll
        for (int j = 0; j < 4; j++) {
            __half2 s = __hmul2(A0h[j], c00);
            s = __hfma2(A1h[j], c10, s);
            s = __hfma2(B0h[j], c01, s);
            s = __hfma2(B1h[j], c11, s);
            float2 fs = __half22float2(s);
            dv[2 * j]     = fs.x;
            dv[2 * j + 1] = fs.y;
        }

        const u64* wp = &sw2[(k * 8) * 8];
#pragma unroll
        for (int ci = 0; ci < 8; ci++) {
            u64 a = pack2(dv[ci], dv[ci]);
            const u64* wc = &wp[ci * 8];
#pragma unroll
            for (int p = 0; p < 8; p++)
                acc2[p] = ffma2(a, wc[p], acc2[p]);
        }
    }

    float acc[16];
#pragma unroll
    for (int p = 0; p < 8; p++) {
        float2 u = unpack2(acc2[p]);
        acc[p] = u.x; acc[p + 8] = u.y;
    }

#pragma unroll
    for (int co = 0; co < 16; co++) g_conv[co * V + v] = acc[co];

    int lane = tid & 31;
#pragma unroll
    for (int g = 0; g < 4; g++) {
        float s = acc[4 * g] + acc[4 * g + 1] + acc[4 * g + 2] + acc[4 * g + 3];
        float q = acc[4 * g] * acc[4 * g] + acc[4 * g + 1] * acc[4 * g + 1]
                + acc[4 * g + 2] * acc[4 * g + 2] + acc[4 * g + 3] * acc[4 * g + 3];
#pragma unroll
        for (int off = 16; off; off >>= 1) {
            s += __shfl_down_sync(0xFFFFFFFFu, s, off);
            q += __shfl_down_sync(0xFFFFFFFFu, q, off);
        }
        if (lane == 0) {
            atomicAdd(&g_gsum[g], s);
            atomicAdd(&g_gsq[g], q);
        }
    }
}

// ---------------- kernel 4: GN-finalize prologue + apply GN + ReLU ----------------
__global__ void k_gn_apply(float* __restrict__ out,
                           const float* __restrict__ gng,
                           const float* __restrict__ gnb) {
    __shared__ float sgs[16], sgt[16];
    int tid = threadIdx.x;
    if (tid < 16) {
        int g = tid >> 2;
        float inv = 1.0f / (4.0f * (float)V);
        float mean = g_gsum[g] * inv;
        float var  = g_gsq[g] * inv - mean * mean;
        float s = gng[tid] * rsqrtf(var + EPSV);
        sgs[tid] = s;
        sgt[tid] = gnb[tid] - mean * s;
    }
    __syncthreads();

    int i4 = blockIdx.x * 256 + tid;
    int co = (i4 * 4) >> 18;
    float s = sgs[co], t = sgt[co];
    float4 a = reinterpret_cast<const float4*>(g_conv)[i4];
    float4 r;
    r.x = fmaxf(fmaf(a.x, s, t), 0.f);
    r.y = fmaxf(fmaf(a.y, s, t), 0.f);
    r.z = fmaxf(fmaf(a.z, s, t), 0.f);
    r.w = fmaxf(fmaf(a.w, s, t), 0.f);
    reinterpret_cast<float4*>(out)[i4] = r;
}

// ---------------- launch ----------------
extern "C" void kernel_launch(void* const* d_in, const int* in_sizes, int n_in,
                              void* d_out, int out_size) {
    (void)in_sizes; (void)n_in; (void)out_size;
    const float* f    = (const float*)d_in[0];
    const float* offw = (const float*)d_in[1];
    const float* offb = (const float*)d_in[2];
    const float* bng  = (const float*)d_in[3];
    const float* bnb  = (const float*)d_in[4];
    const float* dcnw = (const float*)d_in[5];
    const float* dcnb = (const float*)d_in[6];
    const float* gng  = (const float*)d_in[7];
    const float* gnb  = (const float*)d_in[8];
    float* out = (float*)d_out;

    k_transpose<<<(PV + 255) / 256, 256>>>(f);
    k_conv_off<<<512, 256>>>(offw, offb);
    k_main<<<1024, 256>>>(dcnw, dcnb, bng, bnb);
    k_gn_apply<<<4096, 256>>>(out, gng, gnb);
}

// round 16
// speedup vs baseline: 1.0205x; 1.0205x over previous
#include <cuda_runtime.h>
#include <cuda_fp16.h>
#include <math.h>

#define V    262144         // 64^3
#define PD   66             // padded dim
#define PS   (PD*PD)        // 4356
#define PV   (PD*PD*PD)     // 287496
#define PBASE (PS + PD + 1) // offset of voxel (0,0,0) in padded volume
#define EPSV 1e-5f

typedef unsigned long long u64;

__device__ __forceinline__ u64 ffma2(u64 a, u64 b, u64 c) {
    u64 d;
    asm("fma.rn.f32x2 %0, %1, %2, %3;" : "=l"(d) : "l"(a), "l"(b), "l"(c));
    return d;
}
__device__ __forceinline__ u64 pack2(float lo, float hi) {
    u64 r;
    asm("mov.b64 %0, {%1, %2};" : "=l"(r) : "f"(lo), "f"(hi));
    return r;
}
__device__ __forceinline__ float2 unpack2(u64 v) {
    float2 r;
    asm("mov.b64 {%0, %1}, %2;" : "=f"(r.x), "=f"(r.y) : "l"(v));
    return r;
}

// ---------------- scratch (__device__ globals; no allocation) ----------------
__device__ float  g_ft[PV * 8];      // zero-padded fp32 feat [z][y][x][8] (conv_off)
__device__ float4 g_fth[PV];         // zero-padded fp16 feat [z][y][x][8 halves] (gather)
__device__ float g_off[18 * V];
__device__ float g_conv[16 * V];
__device__ float g_bnsum[18];
__device__ float g_bnsq[18];
__device__ float g_gsum[4];
__device__ float g_gsq[4];

// ---------------- kernel 1: pad+transpose f -> fp32 & fp16 padded volumes ----------------
__global__ void k_transpose(const float* __restrict__ f) {
    int tid = threadIdx.x;
    if (blockIdx.x == 0 && tid < 22) {
        if (tid < 18) { g_bnsum[tid] = 0.f; g_bnsq[tid] = 0.f; }
        else          { g_gsum[tid - 18] = 0.f; g_gsq[tid - 18] = 0.f; }
    }
    int pv = blockIdx.x * blockDim.x + tid;
    if (pv >= PV) return;
    int z = pv / PS, r = pv % PS, y = r / PD, x = r % PD;
    float4 a = make_float4(0.f, 0.f, 0.f, 0.f), b = a;
    if (z >= 1 && z <= 64 && y >= 1 && y <= 64 && x >= 1 && x <= 64) {
        int v = (((z - 1) << 6) + (y - 1) << 6) + (x - 1);
        a.x = f[0 * V + v]; a.y = f[1 * V + v]; a.z = f[2 * V + v]; a.w = f[3 * V + v];
        b.x = f[4 * V + v]; b.y = f[5 * V + v]; b.z = f[6 * V + v]; b.w = f[7 * V + v];
    }
    float4* dst = reinterpret_cast<float4*>(g_ft);
    dst[pv * 2 + 0] = a;
    dst[pv * 2 + 1] = b;

    float4 hp;
    __half2* hh = reinterpret_cast<__half2*>(&hp);
    hh[0] = __floats2half2_rn(a.x, a.y);
    hh[1] = __floats2half2_rn(a.z, a.w);
    hh[2] = __floats2half2_rn(b.x, b.y);
    hh[3] = __floats2half2_rn(b.z, b.w);
    g_fth[pv] = hp;
}

// ---------------- kernel 2: offset conv3d, lane-pair channel split (R14 version) ----------------
__global__ void __launch_bounds__(256, 2)
k_conv_off(const float* __restrict__ offw, const float* __restrict__ offb) {
    __shared__ u64  sw2[27 * 8 * 9];   // [tap][ci][pair p] = (w[p], w[p+9])
    __shared__ int  srow[9];
    __shared__ u64  sbias2[9];
    int tid = threadIdx.x;
    for (int i = tid; i < 1944; i += 256) {
        int p = i % 9, tc = i / 9, ci = tc % 8, tap = tc / 8;
        sw2[i] = pack2(offw[(p * 8 + ci) * 27 + tap],
                       offw[((p + 9) * 8 + ci) * 27 + tap]);
    }
    if (tid < 9) {
        int dz = tid / 3 - 1, dy = tid % 3 - 1;
        srow[tid] = (dz * PS + dy * PD - 1) * 2;
        sbias2[tid] = pack2(offb[tid], offb[tid + 9]);
    }
    __syncthreads();

    int t    = blockIdx.x * 256 + tid;   // 131072 threads
    int pi   = t >> 1;                   // 65536 voxel-groups of 4
    int half = t & 1;                    // 0: ci 0-3, 1: ci 4-7
    int h4 = (pi & 15) << 2;
    int w  = (pi >> 4) & 63;
    int d  = pi >> 10;
    int pc = (d * PS + w * PD + h4 + PBASE) * 2 + half;
    int v0 = pi << 2;
    int lane = tid & 31;

    const float4* base = reinterpret_cast<const float4*>(g_ft);

    u64 acc2[9][4];
#pragma unroll
    for (int p = 0; p < 9; p++) {
        u64 b = half ? pack2(0.f, 0.f) : sbias2[p];
        acc2[p][0] = b; acc2[p][1] = b; acc2[p][2] = b; acc2[p][3] = b;
    }

#pragma unroll 1
    for (int t9 = 0; t9 < 9; t9++) {
        int rb = pc + srow[t9];
        float4 in4[6];                     // 6 x-positions, this thread's ci-half
#pragma unroll
        for (int j = 0; j < 6; j++) in4[j] = base[rb + 2 * j];
        const float* vals = reinterpret_cast<const float*>(in4);  // vals[pos*4 + c]

#pragma unroll
        for (int dx = 0; dx < 3; dx++) {
#pragma unroll
            for (int c = 0; c < 4; c++) {
                u64 a0 = pack2(vals[(dx + 0) * 4 + c], vals[(dx + 0) * 4 + c]);
                u64 a1 = pack2(vals[(dx + 1) * 4 + c], vals[(dx + 1) * 4 + c]);
                u64 a2 = pack2(vals[(dx + 2) * 4 + c], vals[(dx + 2) * 4 + c]);
                u64 a3 = pack2(vals[(dx + 3) * 4 + c], vals[(dx + 3) * 4 + c]);
                const u64* wp = &sw2[((t9 * 3 + dx) * 8 + half * 4 + c) * 9];
#pragma unroll
                for (int p = 0; p < 9; p++) {
                    u64 wv = wp[p];
                    acc2[p][0] = ffma2(a0, wv, acc2[p][0]);
                    acc2[p][1] = ffma2(a1, wv, acc2[p][1]);
                    acc2[p][2] = ffma2(a2, wv, acc2[p][2]);
                    acc2[p][3] = ffma2(a3, wv, acc2[p][3]);
                }
            }
        }
    }

    // pair combine (float-wise), split store, parity-preserving stats
#pragma unroll
    for (int p = 0; p < 9; p++) {
        float2 q0 = unpack2(acc2[p][0]);
        float2 q1 = unpack2(acc2[p][1]);
        float2 q2 = unpack2(acc2[p][2]);
        float2 q3 = unpack2(acc2[p][3]);
        float f0 = q0.x + __shfl_xor_sync(0xFFFFFFFFu, q0.x, 1);
        float g0 = q0.y + __shfl_xor_sync(0xFFFFFFFFu, q0.y, 1);
        float f1 = q1.x + __shfl_xor_sync(0xFFFFFFFFu, q1.x, 1);
        float g1 = q1.y + __shfl_xor_sync(0xFFFFFFFFu, q1.y, 1);
        float f2 = q2.x + __shfl_xor_sync(0xFFFFFFFFu, q2.x, 1);
        float g2 = q2.y + __shfl_xor_sync(0xFFFFFFFFu, q2.y, 1);
        float f3 = q3.x + __shfl_xor_sync(0xFFFFFFFFu, q3.x, 1);
        float g3 = q3.y + __shfl_xor_sync(0xFFFFFFFFu, q3.y, 1);
        float4 st = half ? make_float4(g0, g1, g2, g3)
                         : make_float4(f0, f1, f2, f3);
        int oc = half ? (p + 9) : p;
        *reinterpret_cast<float4*>(&g_off[oc * V + v0]) = st;

        float s = st.x + st.y + st.z + st.w;
        float q = st.x * st.x + st.y * st.y + st.z * st.z + st.w * st.w;
#pragma unroll
        for (int off = 16; off >= 2; off >>= 1) {
            s += __shfl_xor_sync(0xFFFFFFFFu, s, off);
            q += __shfl_xor_sync(0xFFFFFFFFu, q, off);
        }
        if (lane < 2) {
            atomicAdd(&g_bnsum[oc], s);
            atomicAdd(&g_bnsq[oc], q);
        }
    }
}

// ---------------- kernel 3: BN-finalize prologue + BN+tanh, cumsum,
//                  fp16 gather, FFMA2 dcn conv, GN stats (R14 version) ----------------
__global__ void __launch_bounds__(256, 2)
k_main(const float* __restrict__ dcnw, const float* __restrict__ dcnb,
       const float* __restrict__ bng, const float* __restrict__ bnb) {
    __shared__ u64 sw2[9 * 8 * 8];     // [k][ci][pair p] = (w[p], w[p+8])
    __shared__ u64 sb2[8];
    __shared__ float sbns[18], sbnt[18];
    int tid = threadIdx.x;
    for (int i = tid; i < 576; i += 256) {
        int p = i & 7, kc = i >> 3, ci = kc % 8, k = kc / 8;
        sw2[i] = pack2(dcnw[p * 72 + ci * 9 + k], dcnw[(p + 8) * 72 + ci * 9 + k]);
    }
    if (tid < 8) sb2[tid] = pack2(dcnb[tid], dcnb[tid + 8]);
    if (tid >= 32 && tid < 50) {            // BN finalize on a separate warp
        int j = tid - 32;
        float mean = g_bnsum[j] * (1.0f / V);
        float var  = g_bnsq[j] * (1.0f / V) - mean * mean;
        float s = bng[j] * rsqrtf(var + EPSV);
        sbns[j] = s;
        sbnt[j] = bnb[j] - mean * s;
    }
    __syncthreads();

    int v = blockIdx.x * 256 + tid;
    int h = v & 63, w = (v >> 6) & 63, d = v >> 12;

    float zo[9], yo[9];
#pragma unroll
    for (int j = 0; j < 9; j++)
        zo[j] = tanhf(fmaf(g_off[j * V + v], sbns[j], sbnt[j]));
#pragma unroll
    for (int j = 0; j < 9; j++)
        yo[j] = tanhf(fmaf(g_off[(9 + j) * V + v], sbns[9 + j], sbnt[9 + j]));

#pragma unroll
    for (int k = 5; k < 9; k++) { zo[k] += zo[k - 1]; yo[k] += yo[k - 1]; }
#pragma unroll
    for (int k = 3; k >= 0; k--) { zo[k] += zo[k + 1]; yo[k] += yo[k + 1]; }

    u64 acc2[8];
#pragma unroll
    for (int p = 0; p < 8; p++) acc2[p] = sb2[p];

#pragma unroll
    for (int k = 0; k < 9; k++) {
        float zf = (float)d + zo[k];
        float yf = (float)w + yo[k];
        int   xi = h + k - 4;
        float valid = ((unsigned)xi < 63u) ? 1.f : 0.f;
        int   xc = min(max(xi, 0), 63);

        int zb = (int)floorf(zf);
        int yb = (int)floorf(yf);
        int z0 = min(max(zb, 0), 63),  z1 = min(max(zb + 1, 0), 63);
        int y0 = min(max(yb, 0), 63),  y1 = min(max(yb + 1, 0), 63);

        float wz0 = (float)z1 - zf, wz1 = zf - (float)z0;
        float wy0 = (float)y1 - yf, wy1 = yf - (float)y0;

        __half2 c00 = __float2half2_rn(wz0 * wy0 * valid);
        __half2 c01 = __float2half2_rn(wz0 * wy1 * valid);
        __half2 c10 = __float2half2_rn(wz1 * wy0 * valid);
        __half2 c11 = __float2half2_rn(wz1 * wy1 * valid);

        int zr0 = z0 * PS, zr1 = z1 * PS;
        int yr0 = y0 * PD, yr1 = y1 * PD;
        float4 A = g_fth[zr0 + yr0 + xc + PBASE];
        float4 B = g_fth[zr0 + yr1 + xc + PBASE];
        float4 C = g_fth[zr1 + yr0 + xc + PBASE];
        float4 D = g_fth[zr1 + yr1 + xc + PBASE];
        const __half2* Ah = reinterpret_cast<const __half2*>(&A);
        const __half2* Bh = reinterpret_cast<const __half2*>(&B);
        const __half2* Ch = reinterpret_cast<const __half2*>(&C);
        const __half2* Dh = reinterpret_cast<const __half2*>(&D);

        float dv[8];
#pragma unroll
        for (int j = 0; j < 4; j++) {
            __half2 s = __hmul2(Ah[j], c00);
            s = __hfma2(Bh[j], c01, s);
            s = __hfma2(Ch[j], c10, s);
            s = __hfma2(Dh[j], c11, s);
            float2 fs = __half22float2(s);
            dv[2 * j]     = fs.x;
            dv[2 * j + 1] = fs.y;
        }

        const u64* wp = &sw2[(k * 8) * 8];
#pragma unroll
        for (int ci = 0; ci < 8; ci++) {
            u64 a = pack2(dv[ci], dv[ci]);
            const u64* wc = &wp[ci * 8];
#pragma unroll
            for (int p = 0; p < 8; p++)
                acc2[p] = ffma2(a, wc[p], acc2[p]);
        }
    }

    float acc[16];
#pragma unroll
    for (int p = 0; p < 8; p++) {
        float2 u = unpack2(acc2[p]);
        acc[p] = u.x; acc[p + 8] = u.y;
    }

#pragma unroll
    for (int co = 0; co < 16; co++) g_conv[co * V + v] = acc[co];

    int lane = tid & 31;
#pragma unroll
    for (int g = 0; g < 4; g++) {
        float s = acc[4 * g] + acc[4 * g + 1] + acc[4 * g + 2] + acc[4 * g + 3];
        float q = acc[4 * g] * acc[4 * g] + acc[4 * g + 1] * acc[4 * g + 1]
                + acc[4 * g + 2] * acc[4 * g + 2] + acc[4 * g + 3] * acc[4 * g + 3];
#pragma unroll
        for (int off = 16; off; off >>= 1) {
            s += __shfl_down_sync(0xFFFFFFFFu, s, off);
            q += __shfl_down_sync(0xFFFFFFFFu, q, off);
        }
        if (lane == 0) {
            atomicAdd(&g_gsum[g], s);
            atomicAdd(&g_gsq[g], q);
        }
    }
}

// ---------------- kernel 4: GN-finalize prologue + apply GN + ReLU, 4x batched ----------------
__global__ void __launch_bounds__(256)
k_gn_apply(float* __restrict__ out,
           const float* __restrict__ gng,
           const float* __restrict__ gnb) {
    __shared__ float sgs[16], sgt[16];
    int tid = threadIdx.x;
    if (tid < 16) {
        int g = tid >> 2;
        float inv = 1.0f / (4.0f * (float)V);
        float mean = g_gsum[g] * inv;
        float var  = g_gsq[g] * inv - mean * mean;
        float s = gng[tid] * rsqrtf(var + EPSV);
        sgs[tid] = s;
        sgt[tid] = gnb[tid] - mean * s;
    }
    __syncthreads();

    // 4 independent float4s per thread, batched loads for MLP=4.
    // Stride the 4 within-thread elements by blockDim so warp loads stay coalesced.
    int base = blockIdx.x * 1024 + tid;        // 1024 blocks cover 16*V/4 float4s
    const float4* src = reinterpret_cast<const float4*>(g_conv);
    float4* dst = reinterpret_cast<float4*>(out);

    float4 a0 = src[base];
    float4 a1 = src[base + 256];
    float4 a2 = src[base + 512];
    float4 a3 = src[base + 768];

#pragma unroll
    for (int j = 0; j < 4; j++) {
        int i4 = base + j * 256;
        float4 a = (j == 0) ? a0 : (j == 1) ? a1 : (j == 2) ? a2 : a3;
        int co = (i4 * 4) >> 18;
        float s = sgs[co], t = sgt[co];
        float4 r;
        r.x = fmaxf(fmaf(a.x, s, t), 0.f);
        r.y = fmaxf(fmaf(a.y, s, t), 0.f);
        r.z = fmaxf(fmaf(a.z, s, t), 0.f);
        r.w = fmaxf(fmaf(a.w, s, t), 0.f);
        dst[i4] = r;
    }
}

// ---------------- launch ----------------
extern "C" void kernel_launch(void* const* d_in, const int* in_sizes, int n_in,
                              void* d_out, int out_size) {
    (void)in_sizes; (void)n_in; (void)out_size;
    const float* f    = (const float*)d_in[0];
    const float* offw = (const float*)d_in[1];
    const float* offb = (const float*)d_in[2];
    const float* bng  = (const float*)d_in[3];
    const float* bnb  = (const float*)d_in[4];
    const float* dcnw = (const float*)d_in[5];
    const float* dcnb = (const float*)d_in[6];
    const float* gng  = (const float*)d_in[7];
    const float* gnb  = (const float*)d_in[8];
    float* out = (float*)d_out;

    k_transpose<<<(PV + 255) / 256, 256>>>(f);
    k_conv_off<<<512, 256>>>(offw, offb);
    k_main<<<1024, 256>>>(dcnw, dcnb, bng, bnb);
    k_gn_apply<<<1024, 256>>>(out, gng, gnb);
}

// round 17
// speedup vs baseline: 1.0682x; 1.0468x over previous
#include <cuda_runtime.h>
#include <cuda_fp16.h>
#include <math.h>

#define V    262144         // 64^3
#define PD   66             // padded dim
#define PS   (PD*PD)        // 4356
#define PV   (PD*PD*PD)     // 287496
#define PBASE (PS + PD + 1) // offset of voxel (0,0,0) in padded volume
#define EPSV 1e-5f

typedef unsigned long long u64;

__device__ __forceinline__ u64 ffma2(u64 a, u64 b, u64 c) {
    u64 d;
    asm("fma.rn.f32x2 %0, %1, %2, %3;" : "=l"(d) : "l"(a), "l"(b), "l"(c));
    return d;
}
__device__ __forceinline__ u64 pack2(float lo, float hi) {
    u64 r;
    asm("mov.b64 %0, {%1, %2};" : "=l"(r) : "f"(lo), "f"(hi));
    return r;
}
__device__ __forceinline__ float2 unpack2(u64 v) {
    float2 r;
    asm("mov.b64 {%0, %1}, %2;" : "=f"(r.x), "=f"(r.y) : "l"(v));
    return r;
}

// ---------------- scratch (__device__ globals; no allocation) ----------------
__device__ float4 g_fth[PV];         // zero-padded fp16 feat [z][y][x][8 halves] (gather)
__device__ float g_off[18 * V];
__device__ float g_conv[16 * V];
__device__ float g_bnsum[18];
__device__ float g_bnsq[18];
__device__ float g_gsum[4];
__device__ float g_gsq[4];

// ---------------- kernel 1: pad f -> fp16 padded volume; zero stats ----------------
__global__ void k_transpose(const float* __restrict__ f) {
    int tid = threadIdx.x;
    if (blockIdx.x == 0 && tid < 22) {
        if (tid < 18) { g_bnsum[tid] = 0.f; g_bnsq[tid] = 0.f; }
        else          { g_gsum[tid - 18] = 0.f; g_gsq[tid - 18] = 0.f; }
    }
    int pv = blockIdx.x * blockDim.x + tid;
    if (pv >= PV) return;
    int z = pv / PS, r = pv % PS, y = r / PD, x = r % PD;
    float4 a = make_float4(0.f, 0.f, 0.f, 0.f), b = a;
    if (z >= 1 && z <= 64 && y >= 1 && y <= 64 && x >= 1 && x <= 64) {
        int v = (((z - 1) << 6) + (y - 1) << 6) + (x - 1);
        a.x = f[0 * V + v]; a.y = f[1 * V + v]; a.z = f[2 * V + v]; a.w = f[3 * V + v];
        b.x = f[4 * V + v]; b.y = f[5 * V + v]; b.z = f[6 * V + v]; b.w = f[7 * V + v];
    }
    float4 hp;
    __half2* hh = reinterpret_cast<__half2*>(&hp);
    hh[0] = __floats2half2_rn(a.x, a.y);
    hh[1] = __floats2half2_rn(a.z, a.w);
    hh[2] = __floats2half2_rn(b.x, b.y);
    hh[3] = __floats2half2_rn(b.z, b.w);
    g_fth[pv] = hp;
}

// ---------------- kernel 2: offset conv3d reading f directly, lane-pair ci split ----------------
// Thread pair (even/odd lane) shares 4 voxels; even handles ci 0-3, odd ci 4-7.
// Reads the harness input f [c][z][y][x] with inline bounds predication.
__global__ void __launch_bounds__(256, 2)
k_conv_off(const float* __restrict__ f,
           const float* __restrict__ offw, const float* __restrict__ offb) {
    __shared__ u64  sw2[27 * 8 * 9];   // [tap][ci][pair p] = (w[p], w[p+9])
    __shared__ u64  sbias2[9];
    int tid = threadIdx.x;
    for (int i = tid; i < 1944; i += 256) {
        int p = i % 9, tc = i / 9, ci = tc % 8, tap = tc / 8;
        sw2[i] = pack2(offw[(p * 8 + ci) * 27 + tap],
                       offw[((p + 9) * 8 + ci) * 27 + tap]);
    }
    if (tid < 9) sbias2[tid] = pack2(offb[tid], offb[tid + 9]);
    __syncthreads();

    int t    = blockIdx.x * 256 + tid;   // 131072 threads
    int pi   = t >> 1;                   // 65536 voxel-groups of 4
    int half = t & 1;                    // 0: ci 0-3, 1: ci 4-7
    int h4 = (pi & 15) << 2;
    int w  = (pi >> 4) & 63;
    int d  = pi >> 10;
    int v0 = pi << 2;
    int lane = tid & 31;

    const float* fbase = f + half * 4 * V;   // this thread's 4 channels

    u64 acc2[9][4];
#pragma unroll
    for (int p = 0; p < 9; p++) {
        u64 b = half ? pack2(0.f, 0.f) : sbias2[p];
        acc2[p][0] = b; acc2[p][1] = b; acc2[p][2] = b; acc2[p][3] = b;
    }

#pragma unroll 1
    for (int t9 = 0; t9 < 9; t9++) {
        int zz = d + (t9 / 3) - 1;
        int yy = w + (t9 % 3) - 1;
        bool rv = ((unsigned)zz < 64u) && ((unsigned)yy < 64u);
        int rb = ((zz << 6) + yy) << 6;

        // 6 x-positions x 4 channels, predicated scalar loads
        float vals[6][4];
#pragma unroll
        for (int j = 0; j < 6; j++) {
            int xx = h4 - 1 + j;
            bool xv = rv && ((unsigned)xx < 64u);
#pragma unroll
            for (int c = 0; c < 4; c++)
                vals[j][c] = xv ? fbase[c * V + rb + xx] : 0.f;
        }

#pragma unroll
        for (int dx = 0; dx < 3; dx++) {
#pragma unroll
            for (int c = 0; c < 4; c++) {
                u64 a0 = pack2(vals[dx + 0][c], vals[dx + 0][c]);
                u64 a1 = pack2(vals[dx + 1][c], vals[dx + 1][c]);
                u64 a2 = pack2(vals[dx + 2][c], vals[dx + 2][c]);
                u64 a3 = pack2(vals[dx + 3][c], vals[dx + 3][c]);
                const u64* wp = &sw2[((t9 * 3 + dx) * 8 + half * 4 + c) * 9];
#pragma unroll
                for (int p = 0; p < 9; p++) {
                    u64 wv = wp[p];
                    acc2[p][0] = ffma2(a0, wv, acc2[p][0]);
                    acc2[p][1] = ffma2(a1, wv, acc2[p][1]);
                    acc2[p][2] = ffma2(a2, wv, acc2[p][2]);
                    acc2[p][3] = ffma2(a3, wv, acc2[p][3]);
                }
            }
        }
    }

    // pair combine (float-wise), split store, parity-preserving stats
#pragma unroll
    for (int p = 0; p < 9; p++) {
        float2 q0 = unpack2(acc2[p][0]);
        float2 q1 = unpack2(acc2[p][1]);
        float2 q2 = unpack2(acc2[p][2]);
        float2 q3 = unpack2(acc2[p][3]);
        float f0 = q0.x + __shfl_xor_sync(0xFFFFFFFFu, q0.x, 1);
        float g0 = q0.y + __shfl_xor_sync(0xFFFFFFFFu, q0.y, 1);
        float f1 = q1.x + __shfl_xor_sync(0xFFFFFFFFu, q1.x, 1);
        float g1 = q1.y + __shfl_xor_sync(0xFFFFFFFFu, q1.y, 1);
        float f2 = q2.x + __shfl_xor_sync(0xFFFFFFFFu, q2.x, 1);
        float g2 = q2.y + __shfl_xor_sync(0xFFFFFFFFu, q2.y, 1);
        float f3 = q3.x + __shfl_xor_sync(0xFFFFFFFFu, q3.x, 1);
        float g3 = q3.y + __shfl_xor_sync(0xFFFFFFFFu, q3.y, 1);
        float4 st = half ? make_float4(g0, g1, g2, g3)
                         : make_float4(f0, f1, f2, f3);
        int oc = half ? (p + 9) : p;
        *reinterpret_cast<float4*>(&g_off[oc * V + v0]) = st;

        float s = st.x + st.y + st.z + st.w;
        float q = st.x * st.x + st.y * st.y + st.z * st.z + st.w * st.w;
#pragma unroll
        for (int off = 16; off >= 2; off >>= 1) {
            s += __shfl_xor_sync(0xFFFFFFFFu, s, off);
            q += __shfl_xor_sync(0xFFFFFFFFu, q, off);
        }
        if (lane < 2) {
            atomicAdd(&g_bnsum[oc], s);
            atomicAdd(&g_bnsq[oc], q);
        }
    }
}

// ---------------- kernel 3: BN-finalize prologue + BN+tanh, cumsum,
//                  fp16 gather, FFMA2 dcn conv, GN stats (R14 version) ----------------
__global__ void __launch_bounds__(256, 2)
k_main(const float* __restrict__ dcnw, const float* __restrict__ dcnb,
       const float* __restrict__ bng, const float* __restrict__ bnb) {
    __shared__ u64 sw2[9 * 8 * 8];     // [k][ci][pair p] = (w[p], w[p+8])
    __shared__ u64 sb2[8];
    __shared__ float sbns[18], sbnt[18];
    int tid = threadIdx.x;
    for (int i = tid; i < 576; i += 256) {
        int p = i & 7, kc = i >> 3, ci = kc % 8, k = kc / 8;
        sw2[i] = pack2(dcnw[p * 72 + ci * 9 + k], dcnw[(p + 8) * 72 + ci * 9 + k]);
    }
    if (tid < 8) sb2[tid] = pack2(dcnb[tid], dcnb[tid + 8]);
    if (tid >= 32 && tid < 50) {            // BN finalize on a separate warp
        int j = tid - 32;
        float mean = g_bnsum[j] * (1.0f / V);
        float var  = g_bnsq[j] * (1.0f / V) - mean * mean;
        float s = bng[j] * rsqrtf(var + EPSV);
        sbns[j] = s;
        sbnt[j] = bnb[j] - mean * s;
    }
    __syncthreads();

    int v = blockIdx.x * 256 + tid;
    int h = v & 63, w = (v >> 6) & 63, d = v >> 12;

    float zo[9], yo[9];
#pragma unroll
    for (int j = 0; j < 9; j++)
        zo[j] = tanhf(fmaf(g_off[j * V + v], sbns[j], sbnt[j]));
#pragma unroll
    for (int j = 0; j < 9; j++)
        yo[j] = tanhf(fmaf(g_off[(9 + j) * V + v], sbns[9 + j], sbnt[9 + j]));

#pragma unroll
    for (int k = 5; k < 9; k++) { zo[k] += zo[k - 1]; yo[k] += yo[k - 1]; }
#pragma unroll
    for (int k = 3; k >= 0; k--) { zo[k] += zo[k + 1]; yo[k] += yo[k + 1]; }

    u64 acc2[8];
#pragma unroll
    for (int p = 0; p < 8; p++) acc2[p] = sb2[p];

#pragma unroll
    for (int k = 0; k < 9; k++) {
        float zf = (float)d + zo[k];
        float yf = (float)w + yo[k];
        int   xi = h + k - 4;
        float valid = ((unsigned)xi < 63u) ? 1.f : 0.f;
        int   xc = min(max(xi, 0), 63);

        int zb = (int)floorf(zf);
        int yb = (int)floorf(yf);
        int z0 = min(max(zb, 0), 63),  z1 = min(max(zb + 1, 0), 63);
        int y0 = min(max(yb, 0), 63),  y1 = min(max(yb + 1, 0), 63);

        float wz0 = (float)z1 - zf, wz1 = zf - (float)z0;
        float wy0 = (float)y1 - yf, wy1 = yf - (float)y0;

        __half2 c00 = __float2half2_rn(wz0 * wy0 * valid);
        __half2 c01 = __float2half2_rn(wz0 * wy1 * valid);
        __half2 c10 = __float2half2_rn(wz1 * wy0 * valid);
        __half2 c11 = __float2half2_rn(wz1 * wy1 * valid);

        int zr0 = z0 * PS, zr1 = z1 * PS;
        int yr0 = y0 * PD, yr1 = y1 * PD;
        float4 A = g_fth[zr0 + yr0 + xc + PBASE];
        float4 B = g_fth[zr0 + yr1 + xc + PBASE];
        float4 C = g_fth[zr1 + yr0 + xc + PBASE];
        float4 D = g_fth[zr1 + yr1 + xc + PBASE];
        const __half2* Ah = reinterpret_cast<const __half2*>(&A);
        const __half2* Bh = reinterpret_cast<const __half2*>(&B);
        const __half2* Ch = reinterpret_cast<const __half2*>(&C);
        const __half2* Dh = reinterpret_cast<const __half2*>(&D);

        float dv[8];
#pragma unroll
        for (int j = 0; j < 4; j++) {
            __half2 s = __hmul2(Ah[j], c00);
            s = __hfma2(Bh[j], c01, s);
            s = __hfma2(Ch[j], c10, s);
            s = __hfma2(Dh[j], c11, s);
            float2 fs = __half22float2(s);
            dv[2 * j]     = fs.x;
            dv[2 * j + 1] = fs.y;
        }

        const u64* wp = &sw2[(k * 8) * 8];
#pragma unroll
        for (int ci = 0; ci < 8; ci++) {
            u64 a = pack2(dv[ci], dv[ci]);
            const u64* wc = &wp[ci * 8];
#pragma unroll
            for (int p = 0; p < 8; p++)
                acc2[p] = ffma2(a, wc[p], acc2[p]);
        }
    }

    float acc[16];
#pragma unroll
    for (int p = 0; p < 8; p++) {
        float2 u = unpack2(acc2[p]);
        acc[p] = u.x; acc[p + 8] = u.y;
    }

#pragma unroll
    for (int co = 0; co < 16; co++) g_conv[co * V + v] = acc[co];

    int lane = tid & 31;
#pragma unroll
    for (int g = 0; g < 4; g++) {
        float s = acc[4 * g] + acc[4 * g + 1] + acc[4 * g + 2] + acc[4 * g + 3];
        float q = acc[4 * g] * acc[4 * g] + acc[4 * g + 1] * acc[4 * g + 1]
                + acc[4 * g + 2] * acc[4 * g + 2] + acc[4 * g + 3] * acc[4 * g + 3];
#pragma unroll
        for (int off = 16; off; off >>= 1) {
            s += __shfl_down_sync(0xFFFFFFFFu, s, off);
            q += __shfl_down_sync(0xFFFFFFFFu, q, off);
        }
        if (lane == 0) {
            atomicAdd(&g_gsum[g], s);
            atomicAdd(&g_gsq[g], q);
        }
    }
}

// ---------------- kernel 4: GN-finalize prologue + apply GN + ReLU ----------------
__global__ void __launch_bounds__(256)
k_gn_apply(float* __restrict__ out,
           const float* __restrict__ gng,
           const float* __restrict__ gnb) {
    __shared__ float sgs[16], sgt[16];
    int tid = threadIdx.x;
    if (tid < 16) {
        int g = tid >> 2;
        float inv = 1.0f / (4.0f * (float)V);
        float mean = g_gsum[g] * inv;
        float var  = g_gsq[g] * inv - mean * mean;
        float s = gng[tid] * rsqrtf(var + EPSV);
        sgs[tid] = s;
        sgt[tid] = gnb[tid] - mean * s;
    }
    __syncthreads();

    int base = blockIdx.x * 1024 + tid;        // 1024 blocks cover 16*V/4 float4s
    const float4* src = reinterpret_cast<const float4*>(g_conv);
    float4* dst = reinterpret_cast<float4*>(out);

    float4 a0 = src[base];
    float4 a1 = src[base + 256];
    float4 a2 = src[base + 512];
    float4 a3 = src[base + 768];

#pragma unroll
    for (int j = 0; j < 4; j++) {
        int i4 = base + j * 256;
        float4 a = (j == 0) ? a0 : (j == 1) ? a1 : (j == 2) ? a2 : a3;
        int co = (i4 * 4) >> 18;
        float s = sgs[co], t = sgt[co];
        float4 r;
        r.x = fmaxf(fmaf(a.x, s, t), 0.f);
        r.y = fmaxf(fmaf(a.y, s, t), 0.f);
        r.z = fmaxf(fmaf(a.z, s, t), 0.f);
        r.w = fmaxf(fmaf(a.w, s, t), 0.f);
        dst[i4] = r;
    }
}

// ---------------- launch ----------------
extern "C" void kernel_launch(void* const* d_in, const int* in_sizes, int n_in,
                              void* d_out, int out_size) {
    (void)in_sizes; (void)n_in; (void)out_size;
    const float* f    = (const float*)d_in[0];
    const float* offw = (const float*)d_in[1];
    const float* offb = (const float*)d_in[2];
    const float* bng  = (const float*)d_in[3];
    const float* bnb  = (const float*)d_in[4];
    const float* dcnw = (const float*)d_in[5];
    const float* dcnb = (const float*)d_in[6];
    const float* gng  = (const float*)d_in[7];
    const float* gnb  = (const float*)d_in[8];
    float* out = (float*)d_out;

    k_transpose<<<(PV + 255) / 256, 256>>>(f);
    k_conv_off<<<512, 256>>>(f, offw, offb);
    k_main<<<1024, 256>>>(dcnw, dcnb, bng, bnb);
    k_gn_apply<<<1024, 256>>>(out, gng, gnb);
}